// round 3
// baseline (speedup 1.0000x reference)
#include <cuda_runtime.h>

#define VOCAB 100000
#define D     300
#define KW    5
#define L     128
#define NROW  1024
#define LT    124           // valid conv output length

// scratch (device globals; no allocation allowed)
__device__ float d_cwT[KW * D * D];   // [k][c][o]  transposed conv weights
__device__ float d_Wf [KW * D * D];   // [k*D + d][o]  fused (W1 ∘ conv) weights
__device__ float d_biasf[D];          // fused bias

// ---------------- packed f32x2 helpers ----------------
__device__ __forceinline__ unsigned long long pack2(float lo, float hi) {
    unsigned long long r;
    asm("mov.b64 %0, {%1, %2};" : "=l"(r) : "f"(lo), "f"(hi));
    return r;
}
__device__ __forceinline__ void fma2(unsigned long long& acc,
                                     unsigned long long a, unsigned long long b) {
    asm("fma.rn.f32x2 %0, %1, %2, %0;" : "+l"(acc) : "l"(a), "l"(b));
}
__device__ __forceinline__ float lo32(unsigned long long v) {
    return __uint_as_float((unsigned)(v & 0xffffffffull));
}
__device__ __forceinline__ float hi32(unsigned long long v) {
    return __uint_as_float((unsigned)(v >> 32));
}

// ---------------- kernel 1: transpose conv_w + fused bias ----------------
__global__ void prep_kernel(const float* __restrict__ conv_w,
                            const float* __restrict__ conv_b,
                            const float* __restrict__ b1) {
    int idx = blockIdx.x * blockDim.x + threadIdx.x;
    if (idx < KW * D * D) {
        int o = idx % D;
        int c = (idx / D) % D;
        int k = idx / (D * D);
        d_cwT[idx] = conv_w[(o * D + c) * KW + k];   // cwT[k][c][o]
    }
    if (blockIdx.x == 0 && threadIdx.x < D) {
        int o = threadIdx.x;
        float s = conv_b[o];
        const float* cw = conv_w + (size_t)o * D * KW;
        for (int c = 0; c < D; c++) {
            float bc = b1[c];
            #pragma unroll
            for (int k = 0; k < KW; k++) s += bc * cw[c * KW + k];
        }
        d_biasf[o] = s;
    }
}

// ---------------- kernel 2: Wf[k*D+d][o] = sum_c W1[d][c] * cwT[k][c][o] ----------------
#define DG 8
__global__ void fuse_kernel(const float* __restrict__ W1) {
    __shared__ float w1s[DG][D];
    int k  = blockIdx.x / 38;
    int d0 = (blockIdx.x % 38) * DG;
    int tid = threadIdx.x;
    for (int idx = tid; idx < DG * D; idx += blockDim.x) {
        int q = idx / D, c = idx % D;
        w1s[q][c] = (d0 + q < D) ? W1[(size_t)(d0 + q) * D + c] : 0.f;
    }
    __syncthreads();
    int o = tid;
    if (o < D) {
        float acc[DG];
        #pragma unroll
        for (int q = 0; q < DG; q++) acc[q] = 0.f;
        const float* ct = d_cwT + (size_t)k * D * D + o;
        for (int c = 0; c < D; c++) {
            float cw = ct[(size_t)c * D];
            #pragma unroll
            for (int q = 0; q < DG; q++) acc[q] = fmaf(w1s[q][c], cw, acc[q]);
        }
        #pragma unroll
        for (int q = 0; q < DG; q++)
            if (d0 + q < D) d_Wf[(size_t)(k * D + d0 + q) * D + o] = acc[q];
    }
}

// ---------------- kernel 3: fused gather + conv-GEMM + maxpool + MLP ----------------
// SMEM gathered tile gI: pair-interleaved rows: gI[rr][j] = (g[rr][j], g[rr+64][j])
#define GROWS 68
#define GSTR  602           // floats per gI row (2*300 + 2 pad, kills 4-row bank overlap)
#define KC    30            // reduction chunk (j) per stage
#define WSF   (KC * 64)     // 1920 floats per W tile buffer
#define NSTAGE 50           // 5 k * 10 j-chunks

__global__ void __launch_bounds__(256, 1)
main_kernel(const int*   __restrict__ tok,
            const float* __restrict__ mention,
            const float* __restrict__ emb,
            const float* __restrict__ W2, const float* __restrict__ b2,
            const float* __restrict__ W3, const float* __restrict__ b3,
            float* __restrict__ out) {
    extern __shared__ float sm[];
    float* gI   = sm;                    // 68*602 = 40936
    float* ws   = gI + GROWS * GSTR;     // 2*1920 = 3840
    float* conc = ws + 2 * WSF;          // 600 (cnn_out lands in [0,300))
    float* red  = conc + 600;            // 1024 (reduction buf, reused as h)
    int*   stok = (int*)(red + 1024);    // 128

    const int n   = blockIdx.x;
    const int tid = threadIdx.x;
    const int tx  = tid & 15;
    const int ty  = tid >> 4;

    if (tid < L) stok[tid] = tok[n * L + tid];
    // zero the hi-slot pad (rows 128..131 of the logical g)
    for (int idx = tid; idx < 4 * D; idx += 256)
        gI[(64 + idx / D) * GSTR + (idx % D) * 2 + 1] = 0.f;
    __syncthreads();

    // gather emb rows into pair-interleaved SMEM tile
    for (int idx = tid; idx < L * (D / 4); idx += 256) {
        int r = idx / (D / 4);
        int q = idx % (D / 4);
        const float4 v = __ldg(((const float4*)(emb + (size_t)stok[r] * D)) + q);
        float vv[4] = {v.x, v.y, v.z, v.w};
        int j0 = q * 4;
        #pragma unroll
        for (int u = 0; u < 4; u++) {
            int j = j0 + u;
            if (r < GROWS) gI[r * GSTR + 2 * j]            = vv[u];
            if (r >= 64)   gI[(r - 64) * GSTR + 2 * j + 1] = vv[u];
        }
    }
    __syncthreads();

    // ---- conv GEMM with running max, o-tiles of 64 ----
    for (int ot = 0; ot < 5; ot++) {
        const int ob = ot * 64;

        unsigned long long acc[4][4];
        #pragma unroll
        for (int i = 0; i < 4; i++)
            #pragma unroll
            for (int q = 0; q < 4; q++) acc[i][q] = 0ull;

        // stage 0 load (Wf row base for stage s is simply s*30)
        #pragma unroll
        for (int u = 0; u < 8; u++) {
            int idx = tid + u * 256;
            if (idx < WSF) {
                int o = ob + (idx & 63);
                ws[idx] = (o < D) ? __ldg(&d_Wf[(size_t)(idx >> 6) * D + o]) : 0.f;
            }
        }
        __syncthreads();

        for (int s = 0; s < NSTAGE; s++) {
            // prefetch next stage into registers (latency hidden by compute)
            float pf[8];
            if (s + 1 < NSTAGE) {
                const int r0 = (s + 1) * KC;
                #pragma unroll
                for (int u = 0; u < 8; u++) {
                    int idx = tid + u * 256;
                    float v = 0.f;
                    if (idx < WSF) {
                        int o = ob + (idx & 63);
                        if (o < D) v = __ldg(&d_Wf[(size_t)(r0 + (idx >> 6)) * D + o]);
                    }
                    pf[u] = v;
                }
            }

            const float* wb = ws + (s & 1) * WSF + tx * 4;
            const int k = s / 10;
            const float* gbase = gI + (ty * 4 + k) * GSTR + 2 * ((s % 10) * KC);

            #pragma unroll
            for (int jj = 0; jj < KC; jj++) {
                float4 w = *(const float4*)(wb + jj * 64);
                unsigned long long b0 = pack2(w.x, w.x);
                unsigned long long b1p = pack2(w.y, w.y);
                unsigned long long b2p = pack2(w.z, w.z);
                unsigned long long b3p = pack2(w.w, w.w);
                #pragma unroll
                for (int i = 0; i < 4; i++) {
                    unsigned long long a =
                        *(const unsigned long long*)(gbase + i * GSTR + 2 * jj);
                    fma2(acc[i][0], a, b0);
                    fma2(acc[i][1], a, b1p);
                    fma2(acc[i][2], a, b2p);
                    fma2(acc[i][3], a, b3p);
                }
            }

            if (s + 1 < NSTAGE) {
                float* wo = ws + ((s + 1) & 1) * WSF;
                #pragma unroll
                for (int u = 0; u < 8; u++) {
                    int idx = tid + u * 256;
                    if (idx < WSF) wo[idx] = pf[u];
                }
            }
            __syncthreads();
        }

        // max over t within thread, then across ty groups
        float pm[4];
        #pragma unroll
        for (int q = 0; q < 4; q++) {
            float m = -3.4e38f;
            #pragma unroll
            for (int i = 0; i < 4; i++) {
                m = fmaxf(m, lo32(acc[i][q]));            // t = ty*4+i (< 64, always valid)
                if (ty * 4 + i + 64 < LT)                 // t = ty*4+i+64
                    m = fmaxf(m, hi32(acc[i][q]));
            }
            pm[q] = m;
        }
        *(float4*)(red + ty * 64 + tx * 4) = make_float4(pm[0], pm[1], pm[2], pm[3]);
        __syncthreads();
        if (tid < 64) {
            float m = red[tid];
            #pragma unroll
            for (int yy = 1; yy < 16; yy++) m = fmaxf(m, red[yy * 64 + tid]);
            int o = ob + tid;
            if (o < D) conc[o] = m + d_biasf[o];
        }
        __syncthreads();
    }

    // ---- epilogue: concat, 600x300 tanh GEMV, 300x300 GEMV ----
    for (int idx = tid; idx < D; idx += 256)
        conc[D + idx] = mention[(size_t)n * D + idx];
    __syncthreads();

    float* h = red;
    for (int o = tid; o < D; o += 256) {
        float s = b2[o];
        for (int j = 0; j < 2 * D; j++) s = fmaf(conc[j], W2[(size_t)j * D + o], s);
        h[o] = tanhf(s);
    }
    __syncthreads();
    for (int o = tid; o < D; o += 256) {
        float s = b3[o];
        for (int j = 0; j < D; j++) s = fmaf(h[j], W3[(size_t)j * D + o], s);
        out[(size_t)n * D + o] = s;
    }
}

// ---------------- launch ----------------
extern "C" void kernel_launch(void* const* d_in, const int* in_sizes, int n_in,
                              void* d_out, int out_size) {
    const int*   tok     = (const int*)  d_in[0];
    const float* mention = (const float*)d_in[1];
    const float* emb     = (const float*)d_in[2];
    const float* W1      = (const float*)d_in[3];
    const float* b1      = (const float*)d_in[4];
    const float* conv_w  = (const float*)d_in[5];
    const float* conv_b  = (const float*)d_in[6];
    const float* W2      = (const float*)d_in[7];
    const float* b2      = (const float*)d_in[8];
    const float* W3      = (const float*)d_in[9];
    const float* b3      = (const float*)d_in[10];
    float* out = (float*)d_out;

    const int smem_bytes = (GROWS * GSTR + 2 * WSF + 600 + 1024 + 128) * 4; // 186112
    cudaFuncSetAttribute(main_kernel,
                         cudaFuncAttributeMaxDynamicSharedMemorySize, smem_bytes);

    prep_kernel<<<(KW * D * D + 255) / 256, 256>>>(conv_w, conv_b, b1);
    fuse_kernel<<<KW * 38, 320>>>(W1);
    main_kernel<<<NROW, 256, smem_bytes>>>(tok, mention, emb, W2, b2, W3, b3, out);
}

// round 5
// speedup vs baseline: 2.9153x; 2.9153x over previous
#include <cuda_runtime.h>
#include <cstdint>

#define D 300
#define L 128
#define LT 124
#define KW 5

#define GSTR 316
#define BSTR 168
#define BCHUNK (16*BSTR*4)                 // 10752 B per buffer
#define OFF_G   512
#define OFF_B   (OFF_G + 132*GSTR*4)       // 167360
#define OFF_RED (OFF_B + 2*BCHUNK)         // 188864
#define SMEM_T  (OFF_RED + 8*152*4 + 32)   // 193760

__device__ float d_cwT[KW*D*D];
__device__ float d_Wf[KW*D*D];
__device__ float d_biasf[D];
__device__ float d_Wpk[KW*2*304*152];      // tf32 bits, [k][oph][d 304][o' 152]
__device__ float d_conc[1024*600];

// ---------------- helpers ----------------
__device__ __forceinline__ uint32_t s2u(const void* p){
    uint32_t a; asm("{ .reg .u64 t; cvta.to.shared.u64 t, %1; cvt.u32.u64 %0, t; }":"=r"(a):"l"(p)); return a;
}
__device__ __forceinline__ uint32_t f2tf(float f){
    uint32_t r; asm("cvt.rn.tf32.f32 %0, %1;" : "=r"(r) : "f"(f)); return r;
}
__device__ __forceinline__ uint32_t lds(uint32_t a){
    uint32_t v; asm volatile("ld.shared.b32 %0, [%1];" : "=r"(v) : "r"(a)); return v;
}
__device__ __forceinline__ void mma_tf32(float* c, uint32_t a0, uint32_t a1,
                                         uint32_t a2, uint32_t a3,
                                         uint32_t b0, uint32_t b1){
    asm volatile("mma.sync.aligned.m16n8k8.row.col.f32.tf32.tf32.f32 "
        "{%0,%1,%2,%3}, {%4,%5,%6,%7}, {%8,%9}, {%0,%1,%2,%3};"
        : "+f"(c[0]),"+f"(c[1]),"+f"(c[2]),"+f"(c[3])
        : "r"(a0),"r"(a1),"r"(a2),"r"(a3),"r"(b0),"r"(b1));
}

// ---------------- prep: transpose conv_w (coalesced read) ----------------
__global__ void prep_kernel(const float* __restrict__ cw){
    int i = blockIdx.x*256 + threadIdx.x;
    if (i < KW*D*D){
        int k = i%KW, c = (i/KW)%D, o = i/(KW*D);
        d_cwT[(k*D+c)*D+o] = cw[i];
    }
}
__global__ void bias_kernel(const float* __restrict__ cw, const float* __restrict__ cb,
                            const float* __restrict__ b1){
    __shared__ float s[128];
    int o = blockIdx.x; float p = 0.f;
    for (int c = threadIdx.x; c < D; c += 128){
        const float* w = cw + ((size_t)o*D+c)*KW;
        p += b1[c]*(w[0]+w[1]+w[2]+w[3]+w[4]);
    }
    s[threadIdx.x] = p; __syncthreads();
    for (int st = 64; st; st >>= 1){
        if (threadIdx.x < st) s[threadIdx.x] += s[threadIdx.x+st];
        __syncthreads();
    }
    if (threadIdx.x == 0) d_biasf[o] = cb[o] + s[0];
}

// ---------------- fuse: Wf[(k*D+d)*D+o] = sum_c W1[d][c]*cwT[k][c][o] ----------------
__global__ void fuse_kernel(const float* __restrict__ W1){
    __shared__ float w1s[8][D];
    int k = blockIdx.x/38, d0 = (blockIdx.x%38)*8, tid = threadIdx.x;
    for (int i = tid; i < 8*D; i += blockDim.x){
        int q = i/D, c = i%D;
        w1s[q][c] = (d0+q < D) ? W1[(size_t)(d0+q)*D+c] : 0.f;
    }
    __syncthreads();
    if (tid < D){
        float a[8];
        #pragma unroll
        for (int q = 0; q < 8; q++) a[q] = 0.f;
        const float* ct = d_cwT + (size_t)k*D*D + tid;
        for (int c = 0; c < D; c++){
            float v = ct[(size_t)c*D];
            #pragma unroll
            for (int q = 0; q < 8; q++) a[q] = fmaf(w1s[q][c], v, a[q]);
        }
        #pragma unroll
        for (int q = 0; q < 8; q++)
            if (d0+q < D) d_Wf[(size_t)(k*D+d0+q)*D + tid] = a[q];
    }
}

// ---------------- pack: Wf -> tf32 bits, [k][oph][d 304][o' 152] ----------------
__global__ void pack_kernel(){
    int i = blockIdx.x*256 + threadIdx.x;
    if (i >= KW*2*304*152) return;
    int op = i % 152;
    int dd = (i/152) % 304;
    int oph = (i/152/304) % 2;
    int k = i/(152*304*2);
    int o = oph*152 + op;
    float w = (dd < D && o < D) ? d_Wf[(size_t)(k*D+dd)*D + o] : 0.f;
    uint32_t t = f2tf(w);
    ((uint32_t*)d_Wpk)[i] = t;
}

// ---------------- main: gather + tf32 conv-GEMM + maxpool ----------------
__device__ __forceinline__ void load_chunk(uint32_t sb, int oph, int k, int dc,
                                           int buf, int tid){
    const float* src = d_Wpk + ((size_t)((k*2 + oph)*304) + dc*16)*152;
    uint32_t dst = sb + OFF_B + buf*BCHUNK;
    #pragma unroll
    for (int u = 0; u < 3; u++){
        int i = tid + u*256;
        if (i < 608){                       // 16 rows x 38 uint4
            int row = i/38, w = i - row*38;
            uint32_t da = dst + (uint32_t)(row*BSTR + w*4)*4;
            const float* sa = src + row*152 + w*4;
            asm volatile("cp.async.cg.shared.global [%0], [%1], 16;"
                         :: "r"(da), "l"(sa) : "memory");
        }
    }
}

__global__ void __launch_bounds__(256,1)
main_kernel(const int* __restrict__ tok, const float* __restrict__ mention,
            const float* __restrict__ emb){
    extern __shared__ char sm[];
    const uint32_t sb = s2u(sm);
    const int n = blockIdx.x, tid = threadIdx.x, wid = tid>>5, lane = tid&31;

    if (tid < L) ((int*)sm)[tid] = tok[n*L + tid];
    // zero pads: cols 300..315 of rows 0..127, and rows 128..131 fully
    for (int i = tid; i < 128*16; i += 256){
        int r = i>>4, w = 300 + (i&15);
        *(uint32_t*)(sm + OFF_G + (uint32_t)(r*GSTR + w)*4) = 0u;
    }
    for (int i = tid; i < 4*GSTR; i += 256)
        *(uint32_t*)(sm + OFF_G + (uint32_t)(128*GSTR + i)*4) = 0u;
    __syncthreads();

    // gather G (fp32 -> tf32 bits), rows t=0..127, cols d=0..299
    {
        const int* stok = (const int*)sm;
        for (int i = tid; i < 128*75; i += 256){
            int r = i/75, q = i - r*75;
            float4 v = __ldg((const float4*)(emb + (size_t)stok[r]*D) + q);
            uint4 t;
            t.x = f2tf(v.x); t.y = f2tf(v.y); t.z = f2tf(v.z); t.w = f2tf(v.w);
            *(uint4*)(sm + OFF_G + (uint32_t)(r*GSTR + q*4)*4) = t;
        }
    }
    __syncthreads();

    float* red = (float*)(sm + OFF_RED);

    for (int oph = 0; oph < 2; oph++){
        float acc[19][4];
        #pragma unroll
        for (int j = 0; j < 19; j++){
            acc[j][0] = acc[j][1] = acc[j][2] = acc[j][3] = 0.f;
        }

        load_chunk(sb, oph, 0, 0, 0, tid);
        asm volatile("cp.async.commit_group;" ::: "memory");

        for (int c = 0; c < 95; c++){
            int k = c/19, d0 = (c - k*19)*16;
            if (c + 1 < 95){
                int k2 = (c+1)/19, dc2 = (c+1) - k2*19;
                load_chunk(sb, oph, k2, dc2, (c+1)&1, tid);
                asm volatile("cp.async.commit_group;" ::: "memory");
                asm volatile("cp.async.wait_group 1;" ::: "memory");
            } else {
                asm volatile("cp.async.wait_group 0;" ::: "memory");
            }
            __syncthreads();

            uint32_t ga0 = sb + OFF_G +
                (uint32_t)((wid*16 + (lane>>2) + k)*GSTR + (lane&3) + d0)*4;
            uint32_t bb0 = sb + OFF_B + (c&1)*BCHUNK +
                (uint32_t)((lane&3)*BSTR + (lane>>2))*4;
            #pragma unroll
            for (int ds = 0; ds < 2; ds++){
                uint32_t ga = ga0 + ds*32;            // +8 d cols
                uint32_t a0 = lds(ga);
                uint32_t a1 = lds(ga + 8*GSTR*4);
                uint32_t a2 = lds(ga + 16);
                uint32_t a3 = lds(ga + 8*GSTR*4 + 16);
                uint32_t bb = bb0 + ds*8*BSTR*4;
                #pragma unroll
                for (int j = 0; j < 19; j++){
                    uint32_t b0 = lds(bb + j*32);
                    uint32_t b1 = lds(bb + j*32 + 4*BSTR*4);
                    mma_tf32(acc[j], a0, a1, a2, a3, b0, b1);
                }
            }
            __syncthreads();
        }

        // maxpool over t
        int r = lane>>2;
        int t0 = wid*16 + r, t1 = t0 + 8;
        #pragma unroll
        for (int j = 0; j < 19; j++){
            float m0 = fmaxf(t0 < LT ? acc[j][0] : -3.4e38f,
                             t1 < LT ? acc[j][2] : -3.4e38f);
            float m1 = fmaxf(t0 < LT ? acc[j][1] : -3.4e38f,
                             t1 < LT ? acc[j][3] : -3.4e38f);
            #pragma unroll
            for (int off = 4; off <= 16; off <<= 1){
                m0 = fmaxf(m0, __shfl_xor_sync(0xffffffffu, m0, off));
                m1 = fmaxf(m1, __shfl_xor_sync(0xffffffffu, m1, off));
            }
            if (lane < 4){
                red[wid*152 + j*8 + 2*lane]     = m0;
                red[wid*152 + j*8 + 2*lane + 1] = m1;
            }
        }
        __syncthreads();
        if (tid < 152){
            float m = red[tid];
            #pragma unroll
            for (int w = 1; w < 8; w++) m = fmaxf(m, red[w*152 + tid]);
            int o = oph*152 + tid;
            if (o < D) d_conc[(size_t)n*600 + o] = m + d_biasf[o];
        }
        __syncthreads();
    }

    for (int i = tid; i < D; i += 256)
        d_conc[(size_t)n*600 + D + i] = mention[(size_t)n*D + i];
}

// ---------------- MLP epilogue: 4 bags per CTA ----------------
__global__ void __launch_bounds__(256,1)
mlp_kernel(const float* __restrict__ W2, const float* __restrict__ b2,
           const float* __restrict__ W3, const float* __restrict__ b3,
           float* __restrict__ out){
    __shared__ float cs[4*600], hs[4*300];
    const int nb = blockIdx.x*4, tid = threadIdx.x;
    for (int i = tid; i < 2400; i += 256) cs[i] = d_conc[(size_t)nb*600 + i];
    __syncthreads();
    for (int o = tid; o < D; o += 256){
        float a0 = b2[o], a1 = a0, a2 = a0, a3 = a0;
        for (int j = 0; j < 600; j++){
            float w = __ldg(&W2[(size_t)j*D + o]);
            a0 = fmaf(cs[j], w, a0);       a1 = fmaf(cs[600+j], w, a1);
            a2 = fmaf(cs[1200+j], w, a2);  a3 = fmaf(cs[1800+j], w, a3);
        }
        hs[o] = tanhf(a0); hs[300+o] = tanhf(a1);
        hs[600+o] = tanhf(a2); hs[900+o] = tanhf(a3);
    }
    __syncthreads();
    for (int o = tid; o < D; o += 256){
        float a0 = b3[o], a1 = a0, a2 = a0, a3 = a0;
        for (int j = 0; j < D; j++){
            float w = __ldg(&W3[(size_t)j*D + o]);
            a0 = fmaf(hs[j], w, a0);      a1 = fmaf(hs[300+j], w, a1);
            a2 = fmaf(hs[600+j], w, a2);  a3 = fmaf(hs[900+j], w, a3);
        }
        out[(size_t)nb*D + o] = a0;       out[(size_t)(nb+1)*D + o] = a1;
        out[(size_t)(nb+2)*D + o] = a2;   out[(size_t)(nb+3)*D + o] = a3;
    }
}

extern "C" void kernel_launch(void* const* d_in, const int* in_sizes, int n_in,
                              void* d_out, int out_size){
    const int*   tok     = (const int*)  d_in[0];
    const float* mention = (const float*)d_in[1];
    const float* emb     = (const float*)d_in[2];
    const float* W1      = (const float*)d_in[3];
    const float* b1      = (const float*)d_in[4];
    const float* conv_w  = (const float*)d_in[5];
    const float* conv_b  = (const float*)d_in[6];
    const float* W2      = (const float*)d_in[7];
    const float* b2      = (const float*)d_in[8];
    const float* W3      = (const float*)d_in[9];
    const float* b3      = (const float*)d_in[10];
    float* out = (float*)d_out;

    cudaFuncSetAttribute(main_kernel, cudaFuncAttributeMaxDynamicSharedMemorySize, SMEM_T);
    prep_kernel<<<(KW*D*D + 255)/256, 256>>>(conv_w);
    bias_kernel<<<D, 128>>>(conv_w, conv_b, b1);
    fuse_kernel<<<KW*38, 320>>>(W1);
    pack_kernel<<<(KW*2*304*152 + 255)/256, 256>>>();
    main_kernel<<<1024, 256, SMEM_T>>>(tok, mention, emb);
    mlp_kernel<<<256, 256>>>(W2, b2, W3, b3, out);
}